// round 1
// baseline (speedup 1.0000x reference)
#include <cuda_runtime.h>
#include <math.h>

// Problem constants
#define BB 8
#define TT 2048
#define CC 1024
#define HH 128

// Scratch for q,k,v projections: [B*T, H] each (8 MB each, static device globals)
__device__ float g_q[BB * TT * HH];
__device__ float g_k[BB * TT * HH];
__device__ float g_v[BB * TT * HH];

// ---------------------------------------------------------------------------
// Kernel 1: QKV projection.  out[r][h] = sum_c x[r][c] * W[h][c]
// GEMM M=16384, N=128, K=1024.  BM=128, BN=128, BK=16, 256 threads, 8x8/thread.
// blockIdx.z selects (Wq->g_q, Wk->g_k, Wv->g_v).
// ---------------------------------------------------------------------------
__global__ __launch_bounds__(256) void qkv_kernel(
    const float* __restrict__ x,
    const float* __restrict__ Wq,
    const float* __restrict__ Wk,
    const float* __restrict__ Wv)
{
    const float* W   = (blockIdx.z == 0) ? Wq : (blockIdx.z == 1) ? Wk : Wv;
    float*       out = (blockIdx.z == 0) ? g_q : (blockIdx.z == 1) ? g_k : g_v;

    __shared__ float As[16][132];   // A transposed: As[k][m], pad 4 for banks/alignment
    __shared__ float Bs[16][132];   // Bs[k][h]

    const int tid = threadIdx.x;
    const int m0  = blockIdx.x * 128;
    const int ty  = tid >> 4;       // 0..15 -> rows ty*8..ty*8+7
    const int tx  = tid & 15;       // 0..15 -> cols tx*8..tx*8+7

    float acc[8][8];
    #pragma unroll
    for (int i = 0; i < 8; i++)
        #pragma unroll
        for (int j = 0; j < 8; j++) acc[i][j] = 0.0f;

    for (int k0 = 0; k0 < CC; k0 += 16) {
        // Load A tile: 128 rows x 16 k  (512 float4, 2 per thread)
        #pragma unroll
        for (int l = 0; l < 2; l++) {
            int idx = tid + l * 256;
            int row = idx >> 2;            // 0..127
            int kq  = (idx & 3) * 4;       // 0,4,8,12
            float4 v = *reinterpret_cast<const float4*>(
                &x[(size_t)(m0 + row) * CC + k0 + kq]);
            As[kq + 0][row] = v.x;
            As[kq + 1][row] = v.y;
            As[kq + 2][row] = v.z;
            As[kq + 3][row] = v.w;
        }
        // Load B tile: W[h][k0..k0+15] -> Bs[k][h]  (512 float4, 2 per thread)
        #pragma unroll
        for (int l = 0; l < 2; l++) {
            int idx = tid + l * 256;
            int h   = idx & 127;
            int kq  = (idx >> 7) * 4;      // combined over l: 0,4,8,12
            float4 v = *reinterpret_cast<const float4*>(
                &W[(size_t)h * CC + k0 + kq]);
            Bs[kq + 0][h] = v.x;
            Bs[kq + 1][h] = v.y;
            Bs[kq + 2][h] = v.z;
            Bs[kq + 3][h] = v.w;
        }
        __syncthreads();

        #pragma unroll
        for (int kk = 0; kk < 16; kk++) {
            float a[8], b[8];
            *reinterpret_cast<float4*>(a)     = *reinterpret_cast<const float4*>(&As[kk][ty * 8]);
            *reinterpret_cast<float4*>(a + 4) = *reinterpret_cast<const float4*>(&As[kk][ty * 8 + 4]);
            *reinterpret_cast<float4*>(b)     = *reinterpret_cast<const float4*>(&Bs[kk][tx * 8]);
            *reinterpret_cast<float4*>(b + 4) = *reinterpret_cast<const float4*>(&Bs[kk][tx * 8 + 4]);
            #pragma unroll
            for (int i = 0; i < 8; i++)
                #pragma unroll
                for (int j = 0; j < 8; j++)
                    acc[i][j] += a[i] * b[j];
        }
        __syncthreads();
    }

    // Write out
    #pragma unroll
    for (int i = 0; i < 8; i++) {
        int row = m0 + ty * 8 + i;
        float4* dst = reinterpret_cast<float4*>(&out[(size_t)row * HH + tx * 8]);
        float4 v0 = make_float4(acc[i][0], acc[i][1], acc[i][2], acc[i][3]);
        float4 v1 = make_float4(acc[i][4], acc[i][5], acc[i][6], acc[i][7]);
        dst[0] = v0;
        dst[1] = v1;
    }
}

// ---------------------------------------------------------------------------
// Kernel 2: causal flash attention, fp32.
// BQ = BKV = 64.  256 threads: (ty 0..15) x (tx 0..15).
// Thread owns S rows {ty+16i} (i<4), S cols {tx+16j} (j<4),
// O rows {ty+16i}, O cols {tx+16jj} (jj<8).
// Shared: Qs[64][132], Ks[64][132], Vs[64][132], Ps[64][65]  (~115 KB dynamic)
// ---------------------------------------------------------------------------
#define QS_STRIDE 132
#define PS_STRIDE 65
#define ATTN_SMEM_BYTES ((3 * 64 * QS_STRIDE + 64 * PS_STRIDE) * 4)

__global__ __launch_bounds__(256) void attn_kernel(float* __restrict__ out)
{
    extern __shared__ float sm[];
    float* Qs = sm;
    float* Ks = Qs + 64 * QS_STRIDE;
    float* Vs = Ks + 64 * QS_STRIDE;
    float* Ps = Vs + 64 * QS_STRIDE;

    const int b  = blockIdx.y;
    const int qt = gridDim.x - 1 - blockIdx.x;  // heavy tiles first
    const int q0 = qt * 64;
    const int tid = threadIdx.x;
    const int ty = tid >> 4;
    const int tx = tid & 15;

    const float* qg = g_q + (size_t)b * TT * HH;
    const float* kg = g_k + (size_t)b * TT * HH;
    const float* vg = g_v + (size_t)b * TT * HH;

    // Load Q tile (64 x 128) -> Qs
    #pragma unroll
    for (int l = 0; l < 8; l++) {
        int idx = tid + l * 256;       // 0..2047 float4 slots
        int row = idx >> 5;            // 0..63
        int col = (idx & 31) * 4;      // 0..124
        float4 v = *reinterpret_cast<const float4*>(&qg[(size_t)(q0 + row) * HH + col]);
        *reinterpret_cast<float4*>(&Qs[row * QS_STRIDE + col]) = v;
    }

    float o[4][8];
    float m_r[4], l_r[4];
    #pragma unroll
    for (int i = 0; i < 4; i++) {
        m_r[i] = -1e30f;
        l_r[i] = 0.0f;
        #pragma unroll
        for (int jj = 0; jj < 8; jj++) o[i][jj] = 0.0f;
    }

    const float sc = 0.08838834764831845f;  // 1/sqrt(128)
    const int nkt = qt + 1;

    for (int kt = 0; kt < nkt; kt++) {
        const int k0 = kt * 64;
        __syncthreads();  // protect previous iteration's Ks/Vs/Ps reads
        // Load K,V tiles
        #pragma unroll
        for (int l = 0; l < 8; l++) {
            int idx = tid + l * 256;
            int row = idx >> 5;
            int col = (idx & 31) * 4;
            *reinterpret_cast<float4*>(&Ks[row * QS_STRIDE + col]) =
                *reinterpret_cast<const float4*>(&kg[(size_t)(k0 + row) * HH + col]);
            *reinterpret_cast<float4*>(&Vs[row * QS_STRIDE + col]) =
                *reinterpret_cast<const float4*>(&vg[(size_t)(k0 + row) * HH + col]);
        }
        __syncthreads();

        // S = (Q K^T) * sc  (4x4 per thread)
        float s[4][4];
        #pragma unroll
        for (int i = 0; i < 4; i++)
            #pragma unroll
            for (int j = 0; j < 4; j++) s[i][j] = 0.0f;

        for (int h = 0; h < HH; h += 4) {
            float4 q[4], k[4];
            #pragma unroll
            for (int i = 0; i < 4; i++)
                q[i] = *reinterpret_cast<const float4*>(&Qs[(ty + 16 * i) * QS_STRIDE + h]);
            #pragma unroll
            for (int j = 0; j < 4; j++)
                k[j] = *reinterpret_cast<const float4*>(&Ks[(tx + 16 * j) * QS_STRIDE + h]);
            #pragma unroll
            for (int i = 0; i < 4; i++)
                #pragma unroll
                for (int j = 0; j < 4; j++) {
                    s[i][j] += q[i].x * k[j].x;
                    s[i][j] += q[i].y * k[j].y;
                    s[i][j] += q[i].z * k[j].z;
                    s[i][j] += q[i].w * k[j].w;
                }
        }

        #pragma unroll
        for (int i = 0; i < 4; i++)
            #pragma unroll
            for (int j = 0; j < 4; j++) s[i][j] *= sc;

        // Causal mask on diagonal tile
        if (kt == qt) {
            #pragma unroll
            for (int i = 0; i < 4; i++) {
                int qi = q0 + ty + 16 * i;
                #pragma unroll
                for (int j = 0; j < 4; j++) {
                    int kj = k0 + tx + 16 * j;
                    if (kj > qi) s[i][j] = -1e30f;
                }
            }
        }

        // Row max (over j, then over 16 tx lanes)
        float mt[4];
        #pragma unroll
        for (int i = 0; i < 4; i++) {
            mt[i] = fmaxf(fmaxf(s[i][0], s[i][1]), fmaxf(s[i][2], s[i][3]));
        }
        #pragma unroll
        for (int off = 8; off > 0; off >>= 1) {
            #pragma unroll
            for (int i = 0; i < 4; i++)
                mt[i] = fmaxf(mt[i], __shfl_xor_sync(0xffffffffu, mt[i], off));
        }

        float alpha[4], lt[4];
        #pragma unroll
        for (int i = 0; i < 4; i++) {
            float mnew = fmaxf(m_r[i], mt[i]);
            alpha[i] = __expf(m_r[i] - mnew);
            m_r[i] = mnew;
            float sum = 0.0f;
            #pragma unroll
            for (int j = 0; j < 4; j++) {
                float p = __expf(s[i][j] - mnew);
                s[i][j] = p;
                sum += p;
            }
            lt[i] = sum;
        }
        #pragma unroll
        for (int off = 8; off > 0; off >>= 1) {
            #pragma unroll
            for (int i = 0; i < 4; i++)
                lt[i] += __shfl_xor_sync(0xffffffffu, lt[i], off);
        }
        #pragma unroll
        for (int i = 0; i < 4; i++) {
            l_r[i] = l_r[i] * alpha[i] + lt[i];
            #pragma unroll
            for (int jj = 0; jj < 8; jj++) o[i][jj] *= alpha[i];
        }

        // Write P tile to shared
        #pragma unroll
        for (int i = 0; i < 4; i++)
            #pragma unroll
            for (int j = 0; j < 4; j++)
                Ps[(ty + 16 * i) * PS_STRIDE + tx + 16 * j] = s[i][j];
        __syncthreads();

        // O += P V
        #pragma unroll 4
        for (int ss = 0; ss < 64; ss++) {
            float p[4];
            #pragma unroll
            for (int i = 0; i < 4; i++) p[i] = Ps[(ty + 16 * i) * PS_STRIDE + ss];
            float v[8];
            #pragma unroll
            for (int jj = 0; jj < 8; jj++) v[jj] = Vs[ss * QS_STRIDE + tx + 16 * jj];
            #pragma unroll
            for (int i = 0; i < 4; i++)
                #pragma unroll
                for (int jj = 0; jj < 8; jj++)
                    o[i][jj] += p[i] * v[jj];
        }
    }

    // Epilogue: out[b][q0+r][c] = o / l
    #pragma unroll
    for (int i = 0; i < 4; i++) {
        float inv = 1.0f / l_r[i];
        int row = q0 + ty + 16 * i;
        #pragma unroll
        for (int jj = 0; jj < 8; jj++) {
            out[((size_t)b * TT + row) * HH + tx + 16 * jj] = o[i][jj] * inv;
        }
    }
}

// ---------------------------------------------------------------------------
extern "C" void kernel_launch(void* const* d_in, const int* in_sizes, int n_in,
                              void* d_out, int out_size)
{
    const float* x  = (const float*)d_in[0];
    const float* Wq = (const float*)d_in[1];
    const float* Wk = (const float*)d_in[2];
    const float* Wv = (const float*)d_in[3];
    float* out = (float*)d_out;

    // Opt-in to >48KB dynamic shared memory for the attention kernel
    // (host-side attribute set; idempotent, not a stream op)
    static bool attr_set = false;
    cudaFuncSetAttribute(attn_kernel, cudaFuncAttributeMaxDynamicSharedMemorySize,
                         ATTN_SMEM_BYTES);
    (void)attr_set;

    // QKV projection: grid (M/128, 1, 3)
    dim3 g1((BB * TT) / 128, 1, 3);
    qkv_kernel<<<g1, 256>>>(x, Wq, Wk, Wv);

    // Attention: grid (T/64, B)
    dim3 g2(TT / 64, BB);
    attn_kernel<<<g2, 256, ATTN_SMEM_BYTES>>>(out);
}

// round 3
// speedup vs baseline: 3.7454x; 3.7454x over previous
#include <cuda_runtime.h>
#include <math.h>
#include <stdint.h>

#define BB 8
#define TT 2048
#define CC 1024
#define HH 128

__device__ float g_q[BB * TT * HH];
__device__ float g_k[BB * TT * HH];
__device__ float g_v[BB * TT * HH];

// ---------------------------------------------------------------------------
// mma.sync tf32 helpers
// ---------------------------------------------------------------------------
__device__ __forceinline__ void mma_tf32(float c[4], const uint32_t a[4], const uint32_t b[2]) {
    asm volatile(
        "mma.sync.aligned.m16n8k8.row.col.f32.tf32.tf32.f32 "
        "{%0,%1,%2,%3}, {%4,%5,%6,%7}, {%8,%9}, {%0,%1,%2,%3};"
        : "+f"(c[0]), "+f"(c[1]), "+f"(c[2]), "+f"(c[3])
        : "r"(a[0]), "r"(a[1]), "r"(a[2]), "r"(a[3]), "r"(b[0]), "r"(b[1]));
}

__device__ __forceinline__ uint32_t f2tf(float f) {
    uint32_t u;
    asm("cvt.rna.tf32.f32 %0, %1;" : "=r"(u) : "f"(f));
    return u;
}
__device__ __forceinline__ float f2tff(float f) { return __uint_as_float(f2tf(f)); }

__device__ __forceinline__ uint32_t smem_u32(const void* p) {
    uint32_t a;
    asm("{ .reg .u64 t; cvta.to.shared.u64 t, %1; cvt.u32.u64 %0, t; }" : "=r"(a) : "l"(p));
    return a;
}

#define CP_ASYNC16(dst, src) \
    asm volatile("cp.async.cg.shared.global [%0], [%1], 16;" :: "r"(dst), "l"(src) : "memory")
#define CP_COMMIT() asm volatile("cp.async.commit_group;" ::: "memory")
#define CP_WAIT0()  asm volatile("cp.async.wait_group 0;" ::: "memory")

// ===========================================================================
// Kernel 1: QKV projection, tf32 mma.sync.
// out[r][h] = sum_c x[r][c] * W[h][c].  M=16384, N=128, K=1024.
// BM=128, BN=128, BK=32. 256 threads = 8 warps (4 M-groups x 2 N-groups),
// warp tile 32x64.  Smem: As[128][36], Bs[128][36], double buffered.
// ===========================================================================
#define QKV_AS 4608              // 128*36 floats
#define QKV_SMEM_FLOATS (4 * QKV_AS)
#define QKV_SMEM_BYTES  (QKV_SMEM_FLOATS * 4)

__global__ __launch_bounds__(256, 2) void qkv_mma_kernel(
    const float* __restrict__ x,
    const float* __restrict__ Wq,
    const float* __restrict__ Wk,
    const float* __restrict__ Wv)
{
    extern __shared__ float sm[];
    const int mat = blockIdx.y;
    const float* W = (mat == 0) ? Wq : (mat == 1) ? Wk : Wv;
    float* out = (mat == 0) ? g_q : (mat == 1) ? g_k : g_v;

    const int tid = threadIdx.x;
    const int wid = tid >> 5;
    const int lid = tid & 31;
    const int g = lid >> 2;
    const int c = lid & 3;
    const int wm = wid & 3;       // M group (32 rows)
    const int wn = wid >> 2;      // N group (64 cols)
    const int m0 = blockIdx.x * 128;

    float acc[2][8][4];
    #pragma unroll
    for (int mi = 0; mi < 2; mi++)
        #pragma unroll
        for (int ni = 0; ni < 8; ni++)
            #pragma unroll
            for (int j = 0; j < 4; j++) acc[mi][ni][j] = 0.0f;

    float4 xr[4], wr[4];

    // ---- tile load into regs ----
    auto loadT = [&](int it) {
        const int k0 = it * 32;
        #pragma unroll
        for (int j = 0; j < 4; j++) {
            int idx = tid + j * 256;          // 0..1023
            int m = idx >> 3;                 // 0..127
            int kq = (idx & 7) << 2;          // 0..28
            xr[j] = *reinterpret_cast<const float4*>(&x[(size_t)(m0 + m) * CC + k0 + kq]);
            wr[j] = *reinterpret_cast<const float4*>(&W[(size_t)m * CC + k0 + kq]);
        }
    };
    auto stsT = [&](int p) {
        float* As = sm + p * QKV_AS;
        float* Bs = sm + 2 * QKV_AS + p * QKV_AS;
        #pragma unroll
        for (int j = 0; j < 4; j++) {
            int idx = tid + j * 256;
            int m = idx >> 3;
            int kq = (idx & 7) << 2;
            uint4 ua = make_uint4(f2tf(xr[j].x), f2tf(xr[j].y), f2tf(xr[j].z), f2tf(xr[j].w));
            uint4 ub = make_uint4(f2tf(wr[j].x), f2tf(wr[j].y), f2tf(wr[j].z), f2tf(wr[j].w));
            *reinterpret_cast<uint4*>(&As[m * 36 + kq]) = ua;
            *reinterpret_cast<uint4*>(&Bs[m * 36 + kq]) = ub;
        }
    };

    loadT(0);
    stsT(0);
    __syncthreads();

    for (int it = 0; it < 32; ++it) {
        const int p = it & 1;
        if (it < 31) loadT(it + 1);

        const uint32_t* A  = reinterpret_cast<const uint32_t*>(sm + p * QKV_AS);
        const uint32_t* Bb = reinterpret_cast<const uint32_t*>(sm + 2 * QKV_AS + p * QKV_AS);

        #pragma unroll
        for (int ks = 0; ks < 4; ks++) {
            const int ko = ks * 8 + c;
            uint32_t a[2][4];
            #pragma unroll
            for (int mi = 0; mi < 2; mi++) {
                int rowA = wm * 32 + mi * 16 + g;
                a[mi][0] = A[rowA * 36 + ko];
                a[mi][1] = A[(rowA + 8) * 36 + ko];
                a[mi][2] = A[rowA * 36 + ko + 4];
                a[mi][3] = A[(rowA + 8) * 36 + ko + 4];
            }
            #pragma unroll
            for (int ni = 0; ni < 8; ni++) {
                uint32_t b[2];
                int rowB = wn * 64 + ni * 8 + g;
                b[0] = Bb[rowB * 36 + ko];
                b[1] = Bb[rowB * 36 + ko + 4];
                mma_tf32(acc[0][ni], a[0], b);
                mma_tf32(acc[1][ni], a[1], b);
            }
        }

        if (it < 31) stsT(p ^ 1);
        __syncthreads();
    }

    // Epilogue: round outputs to tf32 so attention operands are exact tf32.
    #pragma unroll
    for (int mi = 0; mi < 2; mi++) {
        int row0 = m0 + wm * 32 + mi * 16 + g;
        int row1 = row0 + 8;
        #pragma unroll
        for (int ni = 0; ni < 8; ni++) {
            int col = wn * 64 + ni * 8 + 2 * c;
            float2 v0 = make_float2(f2tff(acc[mi][ni][0]), f2tff(acc[mi][ni][1]));
            float2 v1 = make_float2(f2tff(acc[mi][ni][2]), f2tff(acc[mi][ni][3]));
            *reinterpret_cast<float2*>(&out[(size_t)row0 * HH + col]) = v0;
            *reinterpret_cast<float2*>(&out[(size_t)row1 * HH + col]) = v1;
        }
    }
}

// ===========================================================================
// Kernel 2: causal flash attention, tf32 mma.sync.
// BQ=BKV=64, 128 threads (4 warps), warp = 16 q-rows, full N.
// Q frags in regs.  K/V double-buffered via cp.async.  P via smem (aliases Q).
// ===========================================================================
// smem float offsets
#define ATT_QS   0                 // 64 x 132
#define ATT_KS0  8448
#define ATT_KS1  16896
#define ATT_VS0  25344             // 64 x 136
#define ATT_VS1  34048
#define ATT_SMEM_FLOATS 42752
#define ATT_SMEM_BYTES (ATT_SMEM_FLOATS * 4)
#define ATT_PS   0                 // 64 x 68 (aliases Qs after frag load)

__global__ __launch_bounds__(128, 1) void attn_mma_kernel(float* __restrict__ out)
{
    extern __shared__ float sm[];
    uint32_t* su = reinterpret_cast<uint32_t*>(sm);
    const uint32_t sb = smem_u32(sm);

    const int b  = blockIdx.y;
    const int qt = (gridDim.x - 1) - blockIdx.x;   // heavy tiles first
    const int q0 = qt * 64;
    const int tid = threadIdx.x;
    const int wid = tid >> 5;
    const int lid = tid & 31;
    const int g = lid >> 2;
    const int c = lid & 3;
    const int r0w = wid * 16;

    const float* qg = g_q + (size_t)b * TT * HH;
    const float* kg = g_k + (size_t)b * TT * HH;
    const float* vg = g_v + (size_t)b * TT * HH;

    // cp.async a 64x128 f32 tile (2048 16B chunks / 128 threads = 16 each)
    auto cpa_k = [&](int koff, int kt) {
        const float* src = kg + (size_t)(kt * 64) * HH;
        #pragma unroll
        for (int i = 0; i < 16; i++) {
            int idx = tid + i * 128;
            int r = idx >> 5, cc = (idx & 31) * 4;
            CP_ASYNC16(sb + (koff + r * 132 + cc) * 4, src + (size_t)r * HH + cc);
        }
    };
    auto cpa_v = [&](int voff, int kt) {
        const float* src = vg + (size_t)(kt * 64) * HH;
        #pragma unroll
        for (int i = 0; i < 16; i++) {
            int idx = tid + i * 128;
            int r = idx >> 5, cc = (idx & 31) * 4;
            CP_ASYNC16(sb + (voff + r * 136 + cc) * 4, src + (size_t)r * HH + cc);
        }
    };

    // Prologue: Q tile + KV tile 0
    {
        const float* src = qg + (size_t)q0 * HH;
        #pragma unroll
        for (int i = 0; i < 16; i++) {
            int idx = tid + i * 128;
            int r = idx >> 5, cc = (idx & 31) * 4;
            CP_ASYNC16(sb + (ATT_QS + r * 132 + cc) * 4, src + (size_t)r * HH + cc);
        }
    }
    cpa_k(ATT_KS0, 0);
    cpa_v(ATT_VS0, 0);
    CP_COMMIT();
    CP_WAIT0();
    __syncthreads();

    // Q fragments: 16 k-steps x 4 regs (rows r0w+g, r0w+g+8)
    uint32_t qa[16][4];
    {
        const int base0 = ATT_QS + (r0w + g) * 132 + c;
        const int base8 = ATT_QS + (r0w + g + 8) * 132 + c;
        #pragma unroll
        for (int ks = 0; ks < 16; ks++) {
            qa[ks][0] = su[base0 + ks * 8];
            qa[ks][1] = su[base8 + ks * 8];
            qa[ks][2] = su[base0 + ks * 8 + 4];
            qa[ks][3] = su[base8 + ks * 8 + 4];
        }
    }
    __syncthreads();   // Qs dead -> Ps usable

    float o[16][4];
    #pragma unroll
    for (int nt = 0; nt < 16; nt++)
        #pragma unroll
        for (int j = 0; j < 4; j++) o[nt][j] = 0.0f;
    float m0s = -1e30f, m1s = -1e30f, l0 = 0.0f, l1 = 0.0f;

    const float sc = 0.08838834764831845f;   // 1/sqrt(128)
    const int nkt = qt + 1;
    const int grow0 = q0 + r0w + g;
    const int grow1 = grow0 + 8;

    for (int kt = 0; kt < nkt; ++kt) {
        const int p = kt & 1;
        const int ksb = p ? ATT_KS1 : ATT_KS0;
        const int vsb = p ? ATT_VS1 : ATT_VS0;

        if (kt + 1 < nkt) {
            cpa_k(p ? ATT_KS0 : ATT_KS1, kt + 1);
            cpa_v(p ? ATT_VS0 : ATT_VS1, kt + 1);
            CP_COMMIT();
        }

        // ---- S = Q K^T ----
        float sa[8][4];
        #pragma unroll
        for (int nt = 0; nt < 8; nt++)
            #pragma unroll
            for (int j = 0; j < 4; j++) sa[nt][j] = 0.0f;

        #pragma unroll
        for (int ks = 0; ks < 16; ks++) {
            const int ko = ks * 8 + c;
            #pragma unroll
            for (int nt = 0; nt < 8; nt++) {
                uint32_t bfr[2];
                const int rowK = nt * 8 + g;
                bfr[0] = su[ksb + rowK * 132 + ko];
                bfr[1] = su[ksb + rowK * 132 + ko + 4];
                mma_tf32(sa[nt], qa[ks], bfr);
            }
        }

        // scale + causal mask
        const int k0 = kt * 64;
        #pragma unroll
        for (int nt = 0; nt < 8; nt++)
            #pragma unroll
            for (int j = 0; j < 4; j++) sa[nt][j] *= sc;
        if (kt == qt) {
            #pragma unroll
            for (int nt = 0; nt < 8; nt++) {
                int colb = k0 + nt * 8 + 2 * c;
                if (colb     > grow0) sa[nt][0] = -1e30f;
                if (colb + 1 > grow0) sa[nt][1] = -1e30f;
                if (colb     > grow1) sa[nt][2] = -1e30f;
                if (colb + 1 > grow1) sa[nt][3] = -1e30f;
            }
        }

        // row max (per thread, then quad shfl)
        float mt0 = -1e30f, mt1 = -1e30f;
        #pragma unroll
        for (int nt = 0; nt < 8; nt++) {
            mt0 = fmaxf(mt0, fmaxf(sa[nt][0], sa[nt][1]));
            mt1 = fmaxf(mt1, fmaxf(sa[nt][2], sa[nt][3]));
        }
        mt0 = fmaxf(mt0, __shfl_xor_sync(0xffffffffu, mt0, 1));
        mt0 = fmaxf(mt0, __shfl_xor_sync(0xffffffffu, mt0, 2));
        mt1 = fmaxf(mt1, __shfl_xor_sync(0xffffffffu, mt1, 1));
        mt1 = fmaxf(mt1, __shfl_xor_sync(0xffffffffu, mt1, 2));

        const float mn0 = fmaxf(m0s, mt0);
        const float mn1 = fmaxf(m1s, mt1);
        const float al0 = __expf(m0s - mn0);
        const float al1 = __expf(m1s - mn1);
        m0s = mn0; m1s = mn1;

        float lt0 = 0.0f, lt1 = 0.0f;
        #pragma unroll
        for (int nt = 0; nt < 8; nt++) {
            sa[nt][0] = __expf(sa[nt][0] - mn0);
            sa[nt][1] = __expf(sa[nt][1] - mn0);
            sa[nt][2] = __expf(sa[nt][2] - mn1);
            sa[nt][3] = __expf(sa[nt][3] - mn1);
            lt0 += sa[nt][0] + sa[nt][1];
            lt1 += sa[nt][2] + sa[nt][3];
        }
        lt0 += __shfl_xor_sync(0xffffffffu, lt0, 1);
        lt0 += __shfl_xor_sync(0xffffffffu, lt0, 2);
        lt1 += __shfl_xor_sync(0xffffffffu, lt1, 1);
        lt1 += __shfl_xor_sync(0xffffffffu, lt1, 2);
        l0 = l0 * al0 + lt0;
        l1 = l1 * al1 + lt1;

        #pragma unroll
        for (int nt = 0; nt < 16; nt++) {
            o[nt][0] *= al0; o[nt][1] *= al0;
            o[nt][2] *= al1; o[nt][3] *= al1;
        }

        // P -> smem (tf32-rounded).  Warp-private region (rows r0w..r0w+15).
        {
            const int pr0 = ATT_PS + (r0w + g) * 68 + 2 * c;
            const int pr8 = ATT_PS + (r0w + g + 8) * 68 + 2 * c;
            #pragma unroll
            for (int nt = 0; nt < 8; nt++) {
                float2 v0 = make_float2(f2tff(sa[nt][0]), f2tff(sa[nt][1]));
                float2 v1 = make_float2(f2tff(sa[nt][2]), f2tff(sa[nt][3]));
                *reinterpret_cast<float2*>(&sm[pr0 + nt * 8]) = v0;
                *reinterpret_cast<float2*>(&sm[pr8 + nt * 8]) = v1;
            }
        }
        __syncwarp();

        // ---- O += P V ----
        #pragma unroll
        for (int ks2 = 0; ks2 < 8; ks2++) {
            uint32_t pa[4];
            const int pb0 = ATT_PS + (r0w + g) * 68 + ks2 * 8 + c;
            const int pb8 = ATT_PS + (r0w + g + 8) * 68 + ks2 * 8 + c;
            pa[0] = su[pb0];
            pa[1] = su[pb8];
            pa[2] = su[pb0 + 4];
            pa[3] = su[pb8 + 4];
            #pragma unroll
            for (int nt = 0; nt < 16; nt++) {
                uint32_t vb[2];
                vb[0] = su[vsb + (ks2 * 8 + c) * 136 + nt * 8 + g];
                vb[1] = su[vsb + (ks2 * 8 + c + 4) * 136 + nt * 8 + g];
                mma_tf32(o[nt], pa, vb);
            }
        }
        __syncwarp();

        if (kt + 1 < nkt) {
            CP_WAIT0();
            __syncthreads();
        }
    }

    // Epilogue
    const float inv0 = 1.0f / l0;
    const float inv1 = 1.0f / l1;
    #pragma unroll
    for (int nt = 0; nt < 16; nt++) {
        int col = nt * 8 + 2 * c;
        float2 v0 = make_float2(o[nt][0] * inv0, o[nt][1] * inv0);
        float2 v1 = make_float2(o[nt][2] * inv1, o[nt][3] * inv1);
        *reinterpret_cast<float2*>(&out[((size_t)b * TT + grow0) * HH + col]) = v0;
        *reinterpret_cast<float2*>(&out[((size_t)b * TT + grow1) * HH + col]) = v1;
    }
}

// ---------------------------------------------------------------------------
extern "C" void kernel_launch(void* const* d_in, const int* in_sizes, int n_in,
                              void* d_out, int out_size)
{
    const float* x  = (const float*)d_in[0];
    const float* Wq = (const float*)d_in[1];
    const float* Wk = (const float*)d_in[2];
    const float* Wv = (const float*)d_in[3];
    float* out = (float*)d_out;

    cudaFuncSetAttribute(qkv_mma_kernel, cudaFuncAttributeMaxDynamicSharedMemorySize,
                         QKV_SMEM_BYTES);
    cudaFuncSetAttribute(attn_mma_kernel, cudaFuncAttributeMaxDynamicSharedMemorySize,
                         ATT_SMEM_BYTES);

    dim3 g1((BB * TT) / 128, 3);
    qkv_mma_kernel<<<g1, 256, QKV_SMEM_BYTES>>>(x, Wq, Wk, Wv);

    dim3 g2(TT / 64, BB);
    attn_mma_kernel<<<g2, 128, ATT_SMEM_BYTES>>>(out);
}